// round 1
// baseline (speedup 1.0000x reference)
#include <cuda_runtime.h>
#include <math.h>

// Problem constants (fixed by reference setup_inputs)
#define BB 8
#define LL 128
#define HH 768
#define MM (BB*LL)          // 1024 rows

// Scratch: A[(b*L+i), h] = X@W1_top + b1 ; Bt[b, h, j] = (X@W1_bot) transposed
__device__ float g_A[MM * HH];
__device__ float g_Bt[BB * HH * LL];

__global__ void zero_out_kernel(float* out) { out[0] = 0.0f; }

// ----------------------------------------------------------------------------
// Dual GEMM: z=0 -> g_A (+b1), z=1 -> g_Bt (transposed store)
// C[m,h] = sum_k X[m,k] * W1[z*H + k, h]
// Tiles: 64x64, 256 threads, 4x4 per thread, K-chunk 16.
// ----------------------------------------------------------------------------
#define TM 64
#define TN 64
#define TK 16

__global__ __launch_bounds__(256, 2)
void dual_gemm_kernel(const float* __restrict__ X, const float* __restrict__ W1,
                      const float* __restrict__ b1)
{
    __shared__ float Xs[TM * TK];   // [m][k]
    __shared__ float Ws[TK * TN];   // [k][n]

    const int which = blockIdx.z;
    const float* __restrict__ W = W1 + which * HH * HH;
    const int n0 = blockIdx.x * TN;
    const int m0 = blockIdx.y * TM;
    const int t  = threadIdx.x;
    const int tx = t & 15;
    const int ty = t >> 4;

    float acc[4][4];
    #pragma unroll
    for (int r = 0; r < 4; r++)
        #pragma unroll
        for (int c = 0; c < 4; c++) acc[r][c] = 0.0f;

    for (int k0 = 0; k0 < HH; k0 += TK) {
        // Load X tile (64x16) with float4: thread t -> row t/4, cols (t%4)*4..+3
        {
            int r  = t >> 2;
            int c4 = (t & 3) * 4;
            float4 v = *reinterpret_cast<const float4*>(&X[(size_t)(m0 + r) * HH + k0 + c4]);
            *reinterpret_cast<float4*>(&Xs[r * TK + c4]) = v;
        }
        // Load W tile (16x64) with float4: thread t -> k row t/16, cols (t%16)*4..+3
        {
            int r  = t >> 4;
            int c4 = (t & 15) * 4;
            float4 v = *reinterpret_cast<const float4*>(&W[(size_t)(k0 + r) * HH + n0 + c4]);
            *reinterpret_cast<float4*>(&Ws[r * TN + c4]) = v;
        }
        __syncthreads();

        #pragma unroll
        for (int kk = 0; kk < TK; kk++) {
            float4 bv = *reinterpret_cast<const float4*>(&Ws[kk * TN + tx * 4]);
            float bf[4] = {bv.x, bv.y, bv.z, bv.w};
            float av[4];
            #pragma unroll
            for (int r = 0; r < 4; r++) av[r] = Xs[(ty * 4 + r) * TK + kk];
            #pragma unroll
            for (int r = 0; r < 4; r++)
                #pragma unroll
                for (int c = 0; c < 4; c++)
                    acc[r][c] = fmaf(av[r], bf[c], acc[r][c]);
        }
        __syncthreads();
    }

    if (which == 0) {
        #pragma unroll
        for (int r = 0; r < 4; r++) {
            int m = m0 + ty * 4 + r;
            #pragma unroll
            for (int c = 0; c < 4; c++) {
                int h = n0 + tx * 4 + c;
                g_A[(size_t)m * HH + h] = acc[r][c] + b1[h];
            }
        }
    } else {
        #pragma unroll
        for (int r = 0; r < 4; r++) {
            int m = m0 + ty * 4 + r;
            int b = m >> 7;          // m / 128
            int j = m & 127;
            #pragma unroll
            for (int c = 0; c < 4; c++) {
                int h = n0 + tx * 4 + c;
                g_Bt[((size_t)b * HH + h) * LL + j] = acc[r][c];
            }
        }
    }
}

// ----------------------------------------------------------------------------
// Start/end CE losses: one block per (b,i) row. 128 threads, 4 dots of len 768.
// ----------------------------------------------------------------------------
__global__ __launch_bounds__(128)
void startend_kernel(const float* __restrict__ X,
                     const int* __restrict__ sp, const int* __restrict__ ep,
                     const float* __restrict__ Wst, const float* __restrict__ bst,
                     const float* __restrict__ Wen, const float* __restrict__ ben,
                     float* out)
{
    int m = blockIdx.x;
    int tid = threadIdx.x;
    const float* x = X + (size_t)m * HH;

    float s0 = 0.f, s1 = 0.f, e0 = 0.f, e1 = 0.f;
    for (int h = tid; h < HH; h += 128) {
        float xv = x[h];
        s0 = fmaf(xv, Wst[h * 2 + 0], s0);
        s1 = fmaf(xv, Wst[h * 2 + 1], s1);
        e0 = fmaf(xv, Wen[h * 2 + 0], e0);
        e1 = fmaf(xv, Wen[h * 2 + 1], e1);
    }
    #pragma unroll
    for (int off = 16; off > 0; off >>= 1) {
        s0 += __shfl_xor_sync(0xffffffffu, s0, off);
        s1 += __shfl_xor_sync(0xffffffffu, s1, off);
        e0 += __shfl_xor_sync(0xffffffffu, e0, off);
        e1 += __shfl_xor_sync(0xffffffffu, e1, off);
    }
    __shared__ float sh[4][4];
    int warp = tid >> 5, lane = tid & 31;
    if (lane == 0) { sh[0][warp] = s0; sh[1][warp] = s1; sh[2][warp] = e0; sh[3][warp] = e1; }
    __syncthreads();
    if (tid == 0) {
        float l0 = sh[0][0] + sh[0][1] + sh[0][2] + sh[0][3] + bst[0];
        float l1 = sh[1][0] + sh[1][1] + sh[1][2] + sh[1][3] + bst[1];
        float mx = fmaxf(l0, l1);
        float lse = mx + logf(expf(l0 - mx) + expf(l1 - mx));
        float loss_s = lse - (sp[m] == 0 ? l0 : l1);

        float k0v = sh[2][0] + sh[2][1] + sh[2][2] + sh[2][3] + ben[0];
        float k1v = sh[3][0] + sh[3][1] + sh[3][2] + sh[3][3] + ben[1];
        float mx2 = fmaxf(k0v, k1v);
        float lse2 = mx2 + logf(expf(k0v - mx2) + expf(k1v - mx2));
        float loss_e = lse2 - (ep[m] == 0 ? k0v : k1v);

        atomicAdd(out, (loss_s + loss_e) * (1.0f / (float)MM));
    }
}

// ----------------------------------------------------------------------------
// Span loss: one block per (b,i). 128 threads, thread tid = column j.
// logit[i,j] = sum_h gelu(A[b,i,h] + Bt[b,h,j]) * W2[h] + b2
// loss = BCEWithLogits, mean over B*L*L, accumulated into out.
// ----------------------------------------------------------------------------
__global__ __launch_bounds__(128)
void span_kernel(const int* __restrict__ spanp, const float* __restrict__ W2,
                 const float* __restrict__ b2, float* out)
{
    __shared__ float a_sh[HH];
    __shared__ float w2_sh[HH];

    int m = blockIdx.x;     // b*L + i
    int b = m >> 7;
    int tid = threadIdx.x;  // j

    for (int h = tid; h < HH; h += 128) {
        a_sh[h]  = g_A[(size_t)m * HH + h];
        w2_sh[h] = W2[h];
    }
    __syncthreads();

    const float* __restrict__ Bp = g_Bt + (size_t)b * HH * LL + tid;
    float acc = 0.0f;
    #pragma unroll 8
    for (int h = 0; h < HH; h++) {
        float xv = a_sh[h] + Bp[(size_t)h * LL];
        // exact GELU: x * 0.5 * (1 + erf(x / sqrt(2)))
        float g = 0.5f * xv * (1.0f + erff(xv * 0.70710678118654752f));
        acc = fmaf(g, w2_sh[h], acc);
    }
    float logit = acc + b2[0];
    float z = (float)spanp[(size_t)m * LL + tid];
    float loss = fmaxf(logit, 0.0f) - logit * z + log1pf(expf(-fabsf(logit)));

    #pragma unroll
    for (int off = 16; off > 0; off >>= 1)
        loss += __shfl_xor_sync(0xffffffffu, loss, off);

    __shared__ float ws[4];
    if ((tid & 31) == 0) ws[tid >> 5] = loss;
    __syncthreads();
    if (tid == 0)
        atomicAdd(out, (ws[0] + ws[1] + ws[2] + ws[3]) * (1.0f / (float)(MM * LL)));
}

// ----------------------------------------------------------------------------
extern "C" void kernel_launch(void* const* d_in, const int* in_sizes, int n_in,
                              void* d_out, int out_size)
{
    const float* X     = (const float*)d_in[0];   // sequence_output (B,L,H)
    const int*   sp    = (const int*)  d_in[1];   // start_positions (B,L)
    const int*   ep    = (const int*)  d_in[2];   // end_positions (B,L)
    const int*   spanp = (const int*)  d_in[3];   // span_positions (B,L,L)
    const float* Wst   = (const float*)d_in[4];   // W_start (H,2)
    const float* bst   = (const float*)d_in[5];   // b_start (2)
    const float* Wen   = (const float*)d_in[6];   // W_end (H,2)
    const float* ben   = (const float*)d_in[7];   // b_end (2)
    const float* W1    = (const float*)d_in[8];   // W1 (2H,H)
    const float* b1    = (const float*)d_in[9];   // b1 (H)
    const float* W2    = (const float*)d_in[10];  // W2 (H,1)
    const float* b2    = (const float*)d_in[11];  // b2 (1)
    float* out = (float*)d_out;

    zero_out_kernel<<<1, 1>>>(out);

    dim3 grid(HH / TN, MM / TM, 2);   // (12, 16, 2)
    dual_gemm_kernel<<<grid, 256>>>(X, W1, b1);

    startend_kernel<<<MM, 128>>>(X, sp, ep, Wst, bst, Wen, ben, out);
    span_kernel<<<MM, 128>>>(spanp, W2, b2, out);
}

// round 4
// speedup vs baseline: 1.4388x; 1.4388x over previous
#include <cuda_runtime.h>
#include <math.h>

// Problem constants (fixed by reference setup_inputs)
#define BB 8
#define LL 128
#define HH 768
#define MM (BB*LL)          // 1024 rows

// Scratch: A[(b*L+i), h] = X@W1_top + b1 ; Bt[b, h, j] = (X@W1_bot) transposed
__device__ float g_A[MM * HH];
__device__ float g_Bt[BB * HH * LL];

__global__ void zero_out_kernel(float* out) { out[0] = 0.0f; }

// ----------------------------------------------------------------------------
// Dual GEMM: z=0 -> g_A (+b1), z=1 -> g_Bt (transposed store)
// C[m,h] = sum_k X[m,k] * W1[z*H + k, h]
// Tiles: 64x64, 256 threads, 4x4 per thread, K-chunk 16.
// ----------------------------------------------------------------------------
#define TM 64
#define TN 64
#define TK 16

__global__ __launch_bounds__(256, 2)
void dual_gemm_kernel(const float* __restrict__ X, const float* __restrict__ W1,
                      const float* __restrict__ b1)
{
    __shared__ float Xs[TM * TK];   // [m][k]
    __shared__ float Ws[TK * TN];   // [k][n]

    const int which = blockIdx.z;
    const float* __restrict__ W = W1 + which * HH * HH;
    const int n0 = blockIdx.x * TN;
    const int m0 = blockIdx.y * TM;
    const int t  = threadIdx.x;
    const int tx = t & 15;
    const int ty = t >> 4;

    float acc[4][4];
    #pragma unroll
    for (int r = 0; r < 4; r++)
        #pragma unroll
        for (int c = 0; c < 4; c++) acc[r][c] = 0.0f;

    for (int k0 = 0; k0 < HH; k0 += TK) {
        // Load X tile (64x16) with float4: thread t -> row t/4, cols (t%4)*4..+3
        {
            int r  = t >> 2;
            int c4 = (t & 3) * 4;
            float4 v = *reinterpret_cast<const float4*>(&X[(size_t)(m0 + r) * HH + k0 + c4]);
            *reinterpret_cast<float4*>(&Xs[r * TK + c4]) = v;
        }
        // Load W tile (16x64) with float4: thread t -> k row t/16, cols (t%16)*4..+3
        {
            int r  = t >> 4;
            int c4 = (t & 15) * 4;
            float4 v = *reinterpret_cast<const float4*>(&W[(size_t)(k0 + r) * HH + n0 + c4]);
            *reinterpret_cast<float4*>(&Ws[r * TN + c4]) = v;
        }
        __syncthreads();

        #pragma unroll
        for (int kk = 0; kk < TK; kk++) {
            float4 bv = *reinterpret_cast<const float4*>(&Ws[kk * TN + tx * 4]);
            float bf[4] = {bv.x, bv.y, bv.z, bv.w};
            float av[4];
            #pragma unroll
            for (int r = 0; r < 4; r++) av[r] = Xs[(ty * 4 + r) * TK + kk];
            #pragma unroll
            for (int r = 0; r < 4; r++)
                #pragma unroll
                for (int c = 0; c < 4; c++)
                    acc[r][c] = fmaf(av[r], bf[c], acc[r][c]);
        }
        __syncthreads();
    }

    if (which == 0) {
        #pragma unroll
        for (int r = 0; r < 4; r++) {
            int m = m0 + ty * 4 + r;
            #pragma unroll
            for (int c = 0; c < 4; c++) {
                int h = n0 + tx * 4 + c;
                g_A[(size_t)m * HH + h] = acc[r][c] + b1[h];
            }
        }
    } else {
        #pragma unroll
        for (int r = 0; r < 4; r++) {
            int m = m0 + ty * 4 + r;
            int b = m >> 7;          // m / 128
            int j = m & 127;
            #pragma unroll
            for (int c = 0; c < 4; c++) {
                int h = n0 + tx * 4 + c;
                g_Bt[((size_t)b * HH + h) * LL + j] = acc[r][c];
            }
        }
    }
}

// ----------------------------------------------------------------------------
// Start/end CE losses: one block per (b,i) row. 128 threads, 4 dots of len 768.
// ----------------------------------------------------------------------------
__global__ __launch_bounds__(128)
void startend_kernel(const float* __restrict__ X,
                     const int* __restrict__ sp, const int* __restrict__ ep,
                     const float* __restrict__ Wst, const float* __restrict__ bst,
                     const float* __restrict__ Wen, const float* __restrict__ ben,
                     float* out)
{
    int m = blockIdx.x;
    int tid = threadIdx.x;
    const float* x = X + (size_t)m * HH;

    float s0 = 0.f, s1 = 0.f, e0 = 0.f, e1 = 0.f;
    for (int h = tid; h < HH; h += 128) {
        float xv = x[h];
        s0 = fmaf(xv, Wst[h * 2 + 0], s0);
        s1 = fmaf(xv, Wst[h * 2 + 1], s1);
        e0 = fmaf(xv, Wen[h * 2 + 0], e0);
        e1 = fmaf(xv, Wen[h * 2 + 1], e1);
    }
    #pragma unroll
    for (int off = 16; off > 0; off >>= 1) {
        s0 += __shfl_xor_sync(0xffffffffu, s0, off);
        s1 += __shfl_xor_sync(0xffffffffu, s1, off);
        e0 += __shfl_xor_sync(0xffffffffu, e0, off);
        e1 += __shfl_xor_sync(0xffffffffu, e1, off);
    }
    __shared__ float sh[4][4];
    int warp = tid >> 5, lane = tid & 31;
    if (lane == 0) { sh[0][warp] = s0; sh[1][warp] = s1; sh[2][warp] = e0; sh[3][warp] = e1; }
    __syncthreads();
    if (tid == 0) {
        float l0 = sh[0][0] + sh[0][1] + sh[0][2] + sh[0][3] + bst[0];
        float l1 = sh[1][0] + sh[1][1] + sh[1][2] + sh[1][3] + bst[1];
        float mx = fmaxf(l0, l1);
        float lse = mx + logf(expf(l0 - mx) + expf(l1 - mx));
        float loss_s = lse - (sp[m] == 0 ? l0 : l1);

        float k0v = sh[2][0] + sh[2][1] + sh[2][2] + sh[2][3] + ben[0];
        float k1v = sh[3][0] + sh[3][1] + sh[3][2] + sh[3][3] + ben[1];
        float mx2 = fmaxf(k0v, k1v);
        float lse2 = mx2 + logf(expf(k0v - mx2) + expf(k1v - mx2));
        float loss_e = lse2 - (ep[m] == 0 ? k0v : k1v);

        atomicAdd(out, (loss_s + loss_e) * (1.0f / (float)MM));
    }
}

// ----------------------------------------------------------------------------
// Fast GELU via hardware tanh: gelu(x) = 0.5x(1 + tanh(0.79788456(x + 0.044715x^3)))
// tanh.approx.f32 is a single SFU op on sm_75+.
// ----------------------------------------------------------------------------
__device__ __forceinline__ float fast_tanh(float x) {
    float y;
    asm("tanh.approx.f32 %0, %1;" : "=f"(y) : "f"(x));
    return y;
}

__device__ __forceinline__ float gelu_fast(float x) {
    float t  = x * x;
    float u  = x * fmaf(0.035677408136300125f, t, 0.7978845608028654f);
    float th = fast_tanh(u);
    float hx = 0.5f * x;
    return fmaf(hx, th, hx);
}

// ----------------------------------------------------------------------------
// Span loss: one block per (b,i). 128 threads, thread tid = column j.
// logit[i,j] = sum_h gelu(A[b,i,h] + Bt[b,h,j]) * W2[h] + b2
// loss = BCEWithLogits, mean over B*L*L, accumulated into out.
// ----------------------------------------------------------------------------
__global__ __launch_bounds__(128)
void span_kernel(const int* __restrict__ spanp, const float* __restrict__ W2,
                 const float* __restrict__ b2, float* out)
{
    __shared__ __align__(16) float a_sh[HH];
    __shared__ __align__(16) float w2_sh[HH];

    int m = blockIdx.x;     // b*L + i
    int b = m >> 7;
    int tid = threadIdx.x;  // j

    for (int h = tid; h < HH; h += 128) {
        a_sh[h]  = g_A[(size_t)m * HH + h];
        w2_sh[h] = W2[h];
    }
    __syncthreads();

    const float* __restrict__ Bp = g_Bt + (size_t)b * HH * LL + tid;
    float acc0 = 0.f, acc1 = 0.f, acc2 = 0.f, acc3 = 0.f;

    #pragma unroll 2
    for (int h = 0; h < HH; h += 4) {
        float b0 = Bp[0];
        float b1v = Bp[LL];
        float b2v = Bp[2 * LL];
        float b3v = Bp[3 * LL];
        float4 av = *reinterpret_cast<const float4*>(&a_sh[h]);
        float4 wv = *reinterpret_cast<const float4*>(&w2_sh[h]);
        acc0 = fmaf(gelu_fast(av.x + b0),  wv.x, acc0);
        acc1 = fmaf(gelu_fast(av.y + b1v), wv.y, acc1);
        acc2 = fmaf(gelu_fast(av.z + b2v), wv.z, acc2);
        acc3 = fmaf(gelu_fast(av.w + b3v), wv.w, acc3);
        Bp += 4 * LL;
    }

    float logit = ((acc0 + acc1) + (acc2 + acc3)) + b2[0];
    float z = (float)spanp[(size_t)m * LL + tid];
    float loss = fmaxf(logit, 0.0f) - logit * z + log1pf(expf(-fabsf(logit)));

    #pragma unroll
    for (int off = 16; off > 0; off >>= 1)
        loss += __shfl_xor_sync(0xffffffffu, loss, off);

    __shared__ float ws[4];
    if ((tid & 31) == 0) ws[tid >> 5] = loss;
    __syncthreads();
    if (tid == 0)
        atomicAdd(out, (ws[0] + ws[1] + ws[2] + ws[3]) * (1.0f / (float)(MM * LL)));
}

// ----------------------------------------------------------------------------
extern "C" void kernel_launch(void* const* d_in, const int* in_sizes, int n_in,
                              void* d_out, int out_size)
{
    const float* X     = (const float*)d_in[0];   // sequence_output (B,L,H)
    const int*   sp    = (const int*)  d_in[1];   // start_positions (B,L)
    const int*   ep    = (const int*)  d_in[2];   // end_positions (B,L)
    const int*   spanp = (const int*)  d_in[3];   // span_positions (B,L,L)
    const float* Wst   = (const float*)d_in[4];   // W_start (H,2)
    const float* bst   = (const float*)d_in[5];   // b_start (2)
    const float* Wen   = (const float*)d_in[6];   // W_end (H,2)
    const float* ben   = (const float*)d_in[7];   // b_end (2)
    const float* W1    = (const float*)d_in[8];   // W1 (2H,H)
    const float* b1    = (const float*)d_in[9];   // b1 (H)
    const float* W2    = (const float*)d_in[10];  // W2 (H,1)
    const float* b2    = (const float*)d_in[11];  // b2 (1)
    float* out = (float*)d_out;

    zero_out_kernel<<<1, 1>>>(out);

    dim3 grid(HH / TN, MM / TM, 2);   // (12, 16, 2)
    dual_gemm_kernel<<<grid, 256>>>(X, W1, b1);

    startend_kernel<<<MM, 128>>>(X, sp, ep, Wst, bst, Wen, ben, out);
    span_kernel<<<MM, 128>>>(spanp, W2, b2, out);
}

// round 6
// speedup vs baseline: 1.5512x; 1.0781x over previous
#include <cuda_runtime.h>
#include <math.h>

// Problem constants (fixed by reference setup_inputs)
#define BB 8
#define LL 128
#define HH 768
#define MM (BB*LL)          // 1024 rows

// Scratch: A[(b*L+i), h] = X@W1_top + b1 ; Bt[b, h, j] = (X@W1_bot) transposed
__device__ float g_A[MM * HH];
__device__ float g_Bt[BB * HH * LL];

__global__ void zero_out_kernel(float* out) { out[0] = 0.0f; }

// ----------------------------------------------------------------------------
// Dual GEMM: z=0 -> g_A (+b1), z=1 -> g_Bt (transposed store)
// C[m,h] = sum_k X[m,k] * W1[z*H + k, h]
// Tiles: 64x64, 256 threads, 4x4 per thread, K-chunk 16.
// ----------------------------------------------------------------------------
#define TM 64
#define TN 64
#define TK 16

__global__ __launch_bounds__(256, 2)
void dual_gemm_kernel(const float* __restrict__ X, const float* __restrict__ W1,
                      const float* __restrict__ b1)
{
    __shared__ float Xs[TM * TK];   // [m][k]
    __shared__ float Ws[TK * TN];   // [k][n]

    const int which = blockIdx.z;
    const float* __restrict__ W = W1 + which * HH * HH;
    const int n0 = blockIdx.x * TN;
    const int m0 = blockIdx.y * TM;
    const int t  = threadIdx.x;
    const int tx = t & 15;
    const int ty = t >> 4;

    float acc[4][4];
    #pragma unroll
    for (int r = 0; r < 4; r++)
        #pragma unroll
        for (int c = 0; c < 4; c++) acc[r][c] = 0.0f;

    for (int k0 = 0; k0 < HH; k0 += TK) {
        {
            int r  = t >> 2;
            int c4 = (t & 3) * 4;
            float4 v = *reinterpret_cast<const float4*>(&X[(size_t)(m0 + r) * HH + k0 + c4]);
            *reinterpret_cast<float4*>(&Xs[r * TK + c4]) = v;
        }
        {
            int r  = t >> 4;
            int c4 = (t & 15) * 4;
            float4 v = *reinterpret_cast<const float4*>(&W[(size_t)(k0 + r) * HH + n0 + c4]);
            *reinterpret_cast<float4*>(&Ws[r * TN + c4]) = v;
        }
        __syncthreads();

        #pragma unroll
        for (int kk = 0; kk < TK; kk++) {
            float4 bv = *reinterpret_cast<const float4*>(&Ws[kk * TN + tx * 4]);
            float bf[4] = {bv.x, bv.y, bv.z, bv.w};
            float av[4];
            #pragma unroll
            for (int r = 0; r < 4; r++) av[r] = Xs[(ty * 4 + r) * TK + kk];
            #pragma unroll
            for (int r = 0; r < 4; r++)
                #pragma unroll
                for (int c = 0; c < 4; c++)
                    acc[r][c] = fmaf(av[r], bf[c], acc[r][c]);
        }
        __syncthreads();
    }

    if (which == 0) {
        #pragma unroll
        for (int r = 0; r < 4; r++) {
            int m = m0 + ty * 4 + r;
            #pragma unroll
            for (int c = 0; c < 4; c++) {
                int h = n0 + tx * 4 + c;
                g_A[(size_t)m * HH + h] = acc[r][c] + b1[h];
            }
        }
    } else {
        #pragma unroll
        for (int r = 0; r < 4; r++) {
            int m = m0 + ty * 4 + r;
            int b = m >> 7;          // m / 128
            int j = m & 127;
            #pragma unroll
            for (int c = 0; c < 4; c++) {
                int h = n0 + tx * 4 + c;
                g_Bt[((size_t)b * HH + h) * LL + j] = acc[r][c];
            }
        }
    }
}

// ----------------------------------------------------------------------------
// Start/end CE losses: one block per (b,i) row. 128 threads, 4 dots of len 768.
// ----------------------------------------------------------------------------
__global__ __launch_bounds__(128)
void startend_kernel(const float* __restrict__ X,
                     const int* __restrict__ sp, const int* __restrict__ ep,
                     const float* __restrict__ Wst, const float* __restrict__ bst,
                     const float* __restrict__ Wen, const float* __restrict__ ben,
                     float* out)
{
    int m = blockIdx.x;
    int tid = threadIdx.x;
    const float* x = X + (size_t)m * HH;

    float s0 = 0.f, s1 = 0.f, e0 = 0.f, e1 = 0.f;
    for (int h = tid; h < HH; h += 128) {
        float xv = x[h];
        s0 = fmaf(xv, Wst[h * 2 + 0], s0);
        s1 = fmaf(xv, Wst[h * 2 + 1], s1);
        e0 = fmaf(xv, Wen[h * 2 + 0], e0);
        e1 = fmaf(xv, Wen[h * 2 + 1], e1);
    }
    #pragma unroll
    for (int off = 16; off > 0; off >>= 1) {
        s0 += __shfl_xor_sync(0xffffffffu, s0, off);
        s1 += __shfl_xor_sync(0xffffffffu, s1, off);
        e0 += __shfl_xor_sync(0xffffffffu, e0, off);
        e1 += __shfl_xor_sync(0xffffffffu, e1, off);
    }
    __shared__ float sh[4][4];
    int warp = tid >> 5, lane = tid & 31;
    if (lane == 0) { sh[0][warp] = s0; sh[1][warp] = s1; sh[2][warp] = e0; sh[3][warp] = e1; }
    __syncthreads();
    if (tid == 0) {
        float l0 = sh[0][0] + sh[0][1] + sh[0][2] + sh[0][3] + bst[0];
        float l1 = sh[1][0] + sh[1][1] + sh[1][2] + sh[1][3] + bst[1];
        float mx = fmaxf(l0, l1);
        float lse = mx + logf(expf(l0 - mx) + expf(l1 - mx));
        float loss_s = lse - (sp[m] == 0 ? l0 : l1);

        float k0v = sh[2][0] + sh[2][1] + sh[2][2] + sh[2][3] + ben[0];
        float k1v = sh[3][0] + sh[3][1] + sh[3][2] + sh[3][3] + ben[1];
        float mx2 = fmaxf(k0v, k1v);
        float lse2 = mx2 + logf(expf(k0v - mx2) + expf(k1v - mx2));
        float loss_e = lse2 - (ep[m] == 0 ? k0v : k1v);

        atomicAdd(out, (loss_s + loss_e) * (1.0f / (float)MM));
    }
}

// ----------------------------------------------------------------------------
// Fast GELU via hardware tanh
// ----------------------------------------------------------------------------
__device__ __forceinline__ float fast_tanh(float x) {
    float y;
    asm("tanh.approx.f32 %0, %1;" : "=f"(y) : "f"(x));
    return y;
}

__device__ __forceinline__ float gelu_fast(float x) {
    float t  = x * x;
    float u  = x * fmaf(0.035677408136300125f, t, 0.7978845608028654f);
    float th = fast_tanh(u);
    float hx = 0.5f * x;
    return fmaf(hx, th, hx);
}

// ----------------------------------------------------------------------------
// Span loss: one block per (b,i). 256 threads = (j in [0,128)) x (h-half).
// Each thread accumulates 384 h-values; the two halves combine via smem,
// then threads j<128 compute the BCE loss and block-reduce into out.
// Doubles warps/SM vs the 128-thread version to hide L2/MUFU latency.
// ----------------------------------------------------------------------------
#define HHALF (HH / 2)      // 384

__global__ __launch_bounds__(256)
void span_kernel(const int* __restrict__ spanp, const float* __restrict__ W2,
                 const float* __restrict__ b2, float* out)
{
    __shared__ __align__(16) float a_sh[HH];
    __shared__ __align__(16) float w2_sh[HH];
    __shared__ float part[256];

    int m = blockIdx.x;     // b*L + i
    int b = m >> 7;
    int tid = threadIdx.x;
    int j    = tid & 127;
    int half = tid >> 7;

    for (int h = tid; h < HH; h += 256) {
        a_sh[h]  = g_A[(size_t)m * HH + h];
        w2_sh[h] = W2[h];
    }
    __syncthreads();

    const int h0 = half * HHALF;
    const float* __restrict__ Bp = g_Bt + ((size_t)b * HH + h0) * LL + j;
    const float* __restrict__ ap = a_sh + h0;
    const float* __restrict__ wp = w2_sh + h0;

    float acc0 = 0.f, acc1 = 0.f, acc2 = 0.f, acc3 = 0.f;

    #pragma unroll 2
    for (int it = 0; it < HHALF / 4; it++) {
        float b0  = Bp[0];
        float b1v = Bp[LL];
        float b2v = Bp[2 * LL];
        float b3v = Bp[3 * LL];
        float4 av = *reinterpret_cast<const float4*>(ap);
        float4 wv = *reinterpret_cast<const float4*>(wp);
        acc0 = fmaf(gelu_fast(av.x + b0),  wv.x, acc0);
        acc1 = fmaf(gelu_fast(av.y + b1v), wv.y, acc1);
        acc2 = fmaf(gelu_fast(av.z + b2v), wv.z, acc2);
        acc3 = fmaf(gelu_fast(av.w + b3v), wv.w, acc3);
        Bp += 4 * LL;
        ap += 4;
        wp += 4;
    }

    part[tid] = (acc0 + acc1) + (acc2 + acc3);
    __syncthreads();

    if (tid < 128) {
        float logit = part[tid] + part[tid + 128] + b2[0];
        float z = (float)spanp[(size_t)m * LL + tid];
        float loss = fmaxf(logit, 0.0f) - logit * z + log1pf(expf(-fabsf(logit)));

        #pragma unroll
        for (int off = 16; off > 0; off >>= 1)
            loss += __shfl_xor_sync(0xffffffffu, loss, off);

        __shared__ float ws[4];
        if ((tid & 31) == 0) ws[tid >> 5] = loss;
        __syncthreads();
        if (tid == 0)
            atomicAdd(out, (ws[0] + ws[1] + ws[2] + ws[3]) * (1.0f / (float)(MM * LL)));
    }
}

// ----------------------------------------------------------------------------
extern "C" void kernel_launch(void* const* d_in, const int* in_sizes, int n_in,
                              void* d_out, int out_size)
{
    const float* X     = (const float*)d_in[0];   // sequence_output (B,L,H)
    const int*   sp    = (const int*)  d_in[1];   // start_positions (B,L)
    const int*   ep    = (const int*)  d_in[2];   // end_positions (B,L)
    const int*   spanp = (const int*)  d_in[3];   // span_positions (B,L,L)
    const float* Wst   = (const float*)d_in[4];   // W_start (H,2)
    const float* bst   = (const float*)d_in[5];   // b_start (2)
    const float* Wen   = (const float*)d_in[6];   // W_end (H,2)
    const float* ben   = (const float*)d_in[7];   // b_end (2)
    const float* W1    = (const float*)d_in[8];   // W1 (2H,H)
    const float* b1    = (const float*)d_in[9];   // b1 (H)
    const float* W2    = (const float*)d_in[10];  // W2 (H,1)
    const float* b2    = (const float*)d_in[11];  // b2 (1)
    float* out = (float*)d_out;

    zero_out_kernel<<<1, 1>>>(out);

    dim3 grid(HH / TN, MM / TM, 2);   // (12, 16, 2)
    dual_gemm_kernel<<<grid, 256>>>(X, W1, b1);

    startend_kernel<<<MM, 128>>>(X, sp, ep, Wst, bst, Wen, ben, out);
    span_kernel<<<MM, 256>>>(spanp, W2, b2, out);
}

// round 7
// speedup vs baseline: 2.0442x; 1.3178x over previous
#include <cuda_runtime.h>
#include <math.h>
#include <stdint.h>

// Problem constants (fixed by reference setup_inputs)
#define BB 8
#define LL 128
#define HH 768
#define MM (BB*LL)          // 1024 rows

// Scratch: A[(b*L+i), h] = X@W1_top + b1 ; Bt[b, h, j] = (X@W1_bot) transposed
__device__ float g_A[MM * HH];
__device__ float g_Bt[BB * HH * LL];

__global__ void zero_out_kernel(float* out) { out[0] = 0.0f; }

// ----------------------------------------------------------------------------
// tf32 helpers
// ----------------------------------------------------------------------------
__device__ __forceinline__ uint32_t f32_to_tf32(float x) {
    uint32_t y;
    asm("cvt.rna.tf32.f32 %0, %1;" : "=r"(y) : "f"(x));
    return y;
}

__device__ __forceinline__ void mma_tf32_16x8x8(
    float& d0, float& d1, float& d2, float& d3,
    uint32_t a0, uint32_t a1, uint32_t a2, uint32_t a3,
    uint32_t b0, uint32_t b1)
{
    asm volatile(
        "mma.sync.aligned.m16n8k8.row.col.f32.tf32.tf32.f32 "
        "{%0,%1,%2,%3}, {%4,%5,%6,%7}, {%8,%9}, {%0,%1,%2,%3};"
        : "+f"(d0), "+f"(d1), "+f"(d2), "+f"(d3)
        : "r"(a0), "r"(a1), "r"(a2), "r"(a3), "r"(b0), "r"(b1));
}

// ----------------------------------------------------------------------------
// Dual GEMM on tensor cores (tf32 mma.sync): z=0 -> g_A (+b1), z=1 -> g_Bt (T)
// C[m,h] = sum_k X[m,k] * W1[z*H + k, h]
// Block tile 128x64, BK=32, 256 threads = 8 warps (4 in m, 2 in n),
// warp tile 32x32 = 2 m16 tiles x 4 n8 tiles.
// ----------------------------------------------------------------------------
#define GBM 128
#define GBN 64
#define GBK 32
#define XS_STRIDE 36   // pad: fragment A banks = (4g+t)%32, conflict-free
#define WS_STRIDE 72   // pad: fragment B banks = (8t+g)%32, conflict-free

__global__ __launch_bounds__(256)
void dual_gemm_tc_kernel(const float* __restrict__ X, const float* __restrict__ W1,
                         const float* __restrict__ b1)
{
    __shared__ uint32_t Xs[GBM * XS_STRIDE];   // [m][k] as tf32 bits
    __shared__ uint32_t Ws[GBK * WS_STRIDE];   // [k][n] as tf32 bits

    const int which = blockIdx.z;
    const float* __restrict__ W = W1 + which * HH * HH;
    const int n0 = blockIdx.x * GBN;
    const int m0 = blockIdx.y * GBM;
    const int t  = threadIdx.x;

    const int warp = t >> 5;
    const int lane = t & 31;
    const int g   = lane >> 2;   // groupID 0..7
    const int tg  = lane & 3;    // thread-in-group 0..3
    const int wm  = warp >> 1;   // 0..3
    const int wn  = warp & 1;    // 0..1
    const int wmb = wm * 32;     // warp m offset in tile
    const int wnb = wn * 32;     // warp n offset in tile

    float acc[2][4][4];
    #pragma unroll
    for (int mt = 0; mt < 2; mt++)
        #pragma unroll
        for (int nt = 0; nt < 4; nt++)
            #pragma unroll
            for (int c = 0; c < 4; c++) acc[mt][nt][c] = 0.0f;

    for (int k0 = 0; k0 < HH; k0 += GBK) {
        // Fill Xs: 128x32 floats = 4096; 256 threads x 4 passes x float4
        #pragma unroll
        for (int p = 0; p < 4; p++) {
            int i   = p * 1024 + t * 4;
            int row = i >> 5;          // /32
            int col = i & 31;
            float4 v = *reinterpret_cast<const float4*>(&X[(size_t)(m0 + row) * HH + k0 + col]);
            uint32_t* d = &Xs[row * XS_STRIDE + col];
            d[0] = f32_to_tf32(v.x); d[1] = f32_to_tf32(v.y);
            d[2] = f32_to_tf32(v.z); d[3] = f32_to_tf32(v.w);
        }
        // Fill Ws: 32x64 floats = 2048; 256 threads x 2 passes x float4
        #pragma unroll
        for (int p = 0; p < 2; p++) {
            int i = p * 1024 + t * 4;
            int kk = i >> 6;           // /64
            int nn = i & 63;
            float4 v = *reinterpret_cast<const float4*>(&W[(size_t)(k0 + kk) * HH + n0 + nn]);
            uint32_t* d = &Ws[kk * WS_STRIDE + nn];
            d[0] = f32_to_tf32(v.x); d[1] = f32_to_tf32(v.y);
            d[2] = f32_to_tf32(v.z); d[3] = f32_to_tf32(v.w);
        }
        __syncthreads();

        #pragma unroll
        for (int k8 = 0; k8 < GBK; k8 += 8) {
            // A fragments: 2 m-tiles
            uint32_t af[2][4];
            #pragma unroll
            for (int mt = 0; mt < 2; mt++) {
                int r0 = wmb + mt * 16 + g;
                af[mt][0] = Xs[r0 * XS_STRIDE + k8 + tg];
                af[mt][1] = Xs[(r0 + 8) * XS_STRIDE + k8 + tg];
                af[mt][2] = Xs[r0 * XS_STRIDE + k8 + tg + 4];
                af[mt][3] = Xs[(r0 + 8) * XS_STRIDE + k8 + tg + 4];
            }
            // B fragments: 4 n-tiles
            uint32_t bfr[4][2];
            #pragma unroll
            for (int nt = 0; nt < 4; nt++) {
                int c0 = wnb + nt * 8 + g;
                bfr[nt][0] = Ws[(k8 + tg) * WS_STRIDE + c0];
                bfr[nt][1] = Ws[(k8 + tg + 4) * WS_STRIDE + c0];
            }
            #pragma unroll
            for (int mt = 0; mt < 2; mt++)
                #pragma unroll
                for (int nt = 0; nt < 4; nt++)
                    mma_tf32_16x8x8(acc[mt][nt][0], acc[mt][nt][1],
                                    acc[mt][nt][2], acc[mt][nt][3],
                                    af[mt][0], af[mt][1], af[mt][2], af[mt][3],
                                    bfr[nt][0], bfr[nt][1]);
        }
        __syncthreads();
    }

    // Epilogue. Fragment C layout: c0=(g,2tg) c1=(g,2tg+1) c2=(g+8,2tg) c3=(g+8,2tg+1)
    #pragma unroll
    for (int mt = 0; mt < 2; mt++) {
        #pragma unroll
        for (int nt = 0; nt < 4; nt++) {
            int mloc = wmb + mt * 16 + g;
            int hloc = wnb + nt * 8 + 2 * tg;
            #pragma unroll
            for (int c = 0; c < 4; c++) {
                int m = m0 + mloc + ((c >= 2) ? 8 : 0);
                int h = n0 + hloc + (c & 1);
                float v = acc[mt][nt][c];
                if (which == 0) {
                    g_A[(size_t)m * HH + h] = v + b1[h];
                } else {
                    int b = m >> 7;
                    int j = m & 127;
                    g_Bt[((size_t)b * HH + h) * LL + j] = v;
                }
            }
        }
    }
}

// ----------------------------------------------------------------------------
// Start/end CE losses: one block per (b,i) row. 128 threads, 4 dots of len 768.
// ----------------------------------------------------------------------------
__global__ __launch_bounds__(128)
void startend_kernel(const float* __restrict__ X,
                     const int* __restrict__ sp, const int* __restrict__ ep,
                     const float* __restrict__ Wst, const float* __restrict__ bst,
                     const float* __restrict__ Wen, const float* __restrict__ ben,
                     float* out)
{
    int m = blockIdx.x;
    int tid = threadIdx.x;
    const float* x = X + (size_t)m * HH;

    float s0 = 0.f, s1 = 0.f, e0 = 0.f, e1 = 0.f;
    for (int h = tid; h < HH; h += 128) {
        float xv = x[h];
        s0 = fmaf(xv, Wst[h * 2 + 0], s0);
        s1 = fmaf(xv, Wst[h * 2 + 1], s1);
        e0 = fmaf(xv, Wen[h * 2 + 0], e0);
        e1 = fmaf(xv, Wen[h * 2 + 1], e1);
    }
    #pragma unroll
    for (int off = 16; off > 0; off >>= 1) {
        s0 += __shfl_xor_sync(0xffffffffu, s0, off);
        s1 += __shfl_xor_sync(0xffffffffu, s1, off);
        e0 += __shfl_xor_sync(0xffffffffu, e0, off);
        e1 += __shfl_xor_sync(0xffffffffu, e1, off);
    }
    __shared__ float sh[4][4];
    int warp = tid >> 5, lane = tid & 31;
    if (lane == 0) { sh[0][warp] = s0; sh[1][warp] = s1; sh[2][warp] = e0; sh[3][warp] = e1; }
    __syncthreads();
    if (tid == 0) {
        float l0 = sh[0][0] + sh[0][1] + sh[0][2] + sh[0][3] + bst[0];
        float l1 = sh[1][0] + sh[1][1] + sh[1][2] + sh[1][3] + bst[1];
        float mx = fmaxf(l0, l1);
        float lse = mx + logf(expf(l0 - mx) + expf(l1 - mx));
        float loss_s = lse - (sp[m] == 0 ? l0 : l1);

        float k0v = sh[2][0] + sh[2][1] + sh[2][2] + sh[2][3] + ben[0];
        float k1v = sh[3][0] + sh[3][1] + sh[3][2] + sh[3][3] + ben[1];
        float mx2 = fmaxf(k0v, k1v);
        float lse2 = mx2 + logf(expf(k0v - mx2) + expf(k1v - mx2));
        float loss_e = lse2 - (ep[m] == 0 ? k0v : k1v);

        atomicAdd(out, (loss_s + loss_e) * (1.0f / (float)MM));
    }
}

// ----------------------------------------------------------------------------
// Fast GELU via hardware tanh
// ----------------------------------------------------------------------------
__device__ __forceinline__ float fast_tanh(float x) {
    float y;
    asm("tanh.approx.f32 %0, %1;" : "=f"(y) : "f"(x));
    return y;
}

__device__ __forceinline__ float gelu_fast(float x) {
    float t  = x * x;
    float u  = x * fmaf(0.035677408136300125f, t, 0.7978845608028654f);
    float th = fast_tanh(u);
    float hx = 0.5f * x;
    return fmaf(hx, th, hx);
}

// ----------------------------------------------------------------------------
// Span loss: one block per (b,i). 256 threads = (j in [0,128)) x (h-half).
// ----------------------------------------------------------------------------
#define HHALF (HH / 2)      // 384

__global__ __launch_bounds__(256)
void span_kernel(const int* __restrict__ spanp, const float* __restrict__ W2,
                 const float* __restrict__ b2, float* out)
{
    __shared__ __align__(16) float a_sh[HH];
    __shared__ __align__(16) float w2_sh[HH];
    __shared__ float part[256];

    int m = blockIdx.x;     // b*L + i
    int b = m >> 7;
    int tid = threadIdx.x;
    int j    = tid & 127;
    int half = tid >> 7;

    for (int h = tid; h < HH; h += 256) {
        a_sh[h]  = g_A[(size_t)m * HH + h];
        w2_sh[h] = W2[h];
    }
    __syncthreads();

    const int h0 = half * HHALF;
    const float* __restrict__ Bp = g_Bt + ((size_t)b * HH + h0) * LL + j;
    const float* __restrict__ ap = a_sh + h0;
    const float* __restrict__ wp = w2_sh + h0;

    float acc0 = 0.f, acc1 = 0.f, acc2 = 0.f, acc3 = 0.f;

    #pragma unroll 2
    for (int it = 0; it < HHALF / 4; it++) {
        float b0  = Bp[0];
        float b1v = Bp[LL];
        float b2v = Bp[2 * LL];
        float b3v = Bp[3 * LL];
        float4 av = *reinterpret_cast<const float4*>(ap);
        float4 wv = *reinterpret_cast<const float4*>(wp);
        acc0 = fmaf(gelu_fast(av.x + b0),  wv.x, acc0);
        acc1 = fmaf(gelu_fast(av.y + b1v), wv.y, acc1);
        acc2 = fmaf(gelu_fast(av.z + b2v), wv.z, acc2);
        acc3 = fmaf(gelu_fast(av.w + b3v), wv.w, acc3);
        Bp += 4 * LL;
        ap += 4;
        wp += 4;
    }

    part[tid] = (acc0 + acc1) + (acc2 + acc3);
    __syncthreads();

    if (tid < 128) {
        float logit = part[tid] + part[tid + 128] + b2[0];
        float z = (float)spanp[(size_t)m * LL + tid];
        float loss = fmaxf(logit, 0.0f) - logit * z + log1pf(expf(-fabsf(logit)));

        #pragma unroll
        for (int off = 16; off > 0; off >>= 1)
            loss += __shfl_xor_sync(0xffffffffu, loss, off);

        __shared__ float ws[4];
        if ((tid & 31) == 0) ws[tid >> 5] = loss;
        __syncthreads();
        if (tid == 0)
            atomicAdd(out, (ws[0] + ws[1] + ws[2] + ws[3]) * (1.0f / (float)(MM * LL)));
    }
}

// ----------------------------------------------------------------------------
extern "C" void kernel_launch(void* const* d_in, const int* in_sizes, int n_in,
                              void* d_out, int out_size)
{
    const float* X     = (const float*)d_in[0];   // sequence_output (B,L,H)
    const int*   sp    = (const int*)  d_in[1];   // start_positions (B,L)
    const int*   ep    = (const int*)  d_in[2];   // end_positions (B,L)
    const int*   spanp = (const int*)  d_in[3];   // span_positions (B,L,L)
    const float* Wst   = (const float*)d_in[4];   // W_start (H,2)
    const float* bst   = (const float*)d_in[5];   // b_start (2)
    const float* Wen   = (const float*)d_in[6];   // W_end (H,2)
    const float* ben   = (const float*)d_in[7];   // b_end (2)
    const float* W1    = (const float*)d_in[8];   // W1 (2H,H)
    const float* b1    = (const float*)d_in[9];   // b1 (H)
    const float* W2    = (const float*)d_in[10];  // W2 (H,1)
    const float* b2    = (const float*)d_in[11];  // b2 (1)
    float* out = (float*)d_out;

    zero_out_kernel<<<1, 1>>>(out);

    dim3 grid(HH / GBN, MM / GBM, 2);   // (12, 8, 2) = 192 blocks
    dual_gemm_tc_kernel<<<grid, 256>>>(X, W1, b1);

    startend_kernel<<<MM, 128>>>(X, sp, ep, Wst, bst, Wen, ben, out);
    span_kernel<<<MM, 256>>>(spanp, W2, b2, out);
}

// round 10
// speedup vs baseline: 2.7488x; 1.3447x over previous
#include <cuda_runtime.h>
#include <math.h>
#include <stdint.h>

// Problem constants (fixed by reference setup_inputs)
#define BB 8
#define LL 128
#define HH 768
#define MM (BB*LL)          // 1024 rows

// Scratch: A[(b*L+i), h] = X@W1_top + b1 ; Bt[b, h, j] = (X@W1_bot) transposed
__device__ float g_A[MM * HH];
__device__ float g_Bt[BB * HH * LL];

__global__ void zero_out_kernel(float* out) { out[0] = 0.0f; }

// ----------------------------------------------------------------------------
// mma.sync tf32 (raw f32 bits in, HW truncates mantissa)
// ----------------------------------------------------------------------------
__device__ __forceinline__ void mma_tf32_16x8x8(
    float& d0, float& d1, float& d2, float& d3,
    uint32_t a0, uint32_t a1, uint32_t a2, uint32_t a3,
    uint32_t b0, uint32_t b1)
{
    asm volatile(
        "mma.sync.aligned.m16n8k8.row.col.f32.tf32.tf32.f32 "
        "{%0,%1,%2,%3}, {%4,%5,%6,%7}, {%8,%9}, {%0,%1,%2,%3};"
        : "+f"(d0), "+f"(d1), "+f"(d2), "+f"(d3)
        : "r"(a0), "r"(a1), "r"(a2), "r"(a3), "r"(b0), "r"(b1));
}

__device__ __forceinline__ void cp_async16(uint32_t smem_addr, const void* gptr) {
    asm volatile("cp.async.ca.shared.global [%0], [%1], 16;\n"
                 :: "r"(smem_addr), "l"(gptr));
}
__device__ __forceinline__ void cp_async_commit() {
    asm volatile("cp.async.commit_group;\n");
}
template <int N>
__device__ __forceinline__ void cp_async_wait() {
    asm volatile("cp.async.wait_group %0;\n" :: "n"(N));
}

// ----------------------------------------------------------------------------
// Dual GEMM on tensor cores, cp.async double-buffered.
// z=0 -> g_A (+b1), z=1 -> g_Bt (transposed store)
// C[m,h] = sum_k X[m,k] * W1[z*H + k, h]
// Block tile 64x64, BK=32, 256 threads = 8 warps (2 in m x 4 in n),
// warp tile 32x16 = 2 m16 tiles x 2 n8 tiles.
// ----------------------------------------------------------------------------
#define GBM 64
#define GBN 64
#define GBK 32
#define NKT (HH / GBK)   // 24
#define XS_STRIDE 36     // pad (mult of 4): A-frag LDS conflict-free
#define WS_STRIDE 72     // pad (mult of 4): B-frag LDS conflict-free

__global__ __launch_bounds__(256)
void dual_gemm_tc_kernel(const float* __restrict__ X, const float* __restrict__ W1,
                         const float* __restrict__ b1)
{
    __shared__ uint32_t Xs[2][GBM * XS_STRIDE];   // raw f32 bits
    __shared__ uint32_t Ws[2][GBK * WS_STRIDE];

    const int which = blockIdx.z;
    const float* __restrict__ W = W1 + which * HH * HH;
    const int n0 = blockIdx.x * GBN;
    const int m0 = blockIdx.y * GBM;
    const int t  = threadIdx.x;

    const int warp = t >> 5;
    const int lane = t & 31;
    const int g   = lane >> 2;   // 0..7
    const int tg  = lane & 3;    // 0..3
    const int wm  = warp & 1;    // 2 warps in m
    const int wn  = warp >> 1;   // 4 warps in n
    const int wmb = wm * 32;
    const int wnb = wn * 16;

    // Per-thread fill coordinates (2 16B chunks for Xs, 2 for Ws per stage)
    const int xr0 = (t * 4) >> 5;            // pass 0: rows 0..31
    const int xc0 = (t * 4) & 31;
    const int xr1 = xr0 + 32;                // pass 1: rows 32..63
    const int wk0 = (t * 4) >> 6;            // pass 0: k 0..15
    const int wn0 = (t * 4) & 63;
    const int wk1 = wk0 + 16;                // pass 1: k 16..31

    auto fill = [&](int buf, int k0) {
        cp_async16((uint32_t)__cvta_generic_to_shared(&Xs[buf][xr0 * XS_STRIDE + xc0]),
                   &X[(size_t)(m0 + xr0) * HH + k0 + xc0]);
        cp_async16((uint32_t)__cvta_generic_to_shared(&Xs[buf][xr1 * XS_STRIDE + xc0]),
                   &X[(size_t)(m0 + xr1) * HH + k0 + xc0]);
        cp_async16((uint32_t)__cvta_generic_to_shared(&Ws[buf][wk0 * WS_STRIDE + wn0]),
                   &W[(size_t)(k0 + wk0) * HH + n0 + wn0]);
        cp_async16((uint32_t)__cvta_generic_to_shared(&Ws[buf][wk1 * WS_STRIDE + wn0]),
                   &W[(size_t)(k0 + wk1) * HH + n0 + wn0]);
    };

    float acc[2][2][4];
    #pragma unroll
    for (int mt = 0; mt < 2; mt++)
        #pragma unroll
        for (int nt = 0; nt < 2; nt++)
            #pragma unroll
            for (int c = 0; c < 4; c++) acc[mt][nt][c] = 0.0f;

    fill(0, 0);
    cp_async_commit();

    for (int kt = 0; kt < NKT; kt++) {
        if (kt + 1 < NKT) {
            fill((kt + 1) & 1, (kt + 1) * GBK);
            cp_async_commit();
            cp_async_wait<1>();
        } else {
            cp_async_wait<0>();
        }
        __syncthreads();

        const uint32_t* xs = Xs[kt & 1];
        const uint32_t* ws = Ws[kt & 1];

        #pragma unroll
        for (int k8 = 0; k8 < GBK; k8 += 8) {
            uint32_t af[2][4];
            #pragma unroll
            for (int mt = 0; mt < 2; mt++) {
                int r0 = wmb + mt * 16 + g;
                af[mt][0] = xs[r0 * XS_STRIDE + k8 + tg];
                af[mt][1] = xs[(r0 + 8) * XS_STRIDE + k8 + tg];
                af[mt][2] = xs[r0 * XS_STRIDE + k8 + tg + 4];
                af[mt][3] = xs[(r0 + 8) * XS_STRIDE + k8 + tg + 4];
            }
            uint32_t bfr[2][2];
            #pragma unroll
            for (int nt = 0; nt < 2; nt++) {
                int c0 = wnb + nt * 8 + g;
                bfr[nt][0] = ws[(k8 + tg) * WS_STRIDE + c0];
                bfr[nt][1] = ws[(k8 + tg + 4) * WS_STRIDE + c0];
            }
            #pragma unroll
            for (int mt = 0; mt < 2; mt++)
                #pragma unroll
                for (int nt = 0; nt < 2; nt++)
                    mma_tf32_16x8x8(acc[mt][nt][0], acc[mt][nt][1],
                                    acc[mt][nt][2], acc[mt][nt][3],
                                    af[mt][0], af[mt][1], af[mt][2], af[mt][3],
                                    bfr[nt][0], bfr[nt][1]);
        }
        __syncthreads();
    }

    // Epilogue. Fragment C layout: c0=(g,2tg) c1=(g,2tg+1) c2=(g+8,2tg) c3=(g+8,2tg+1)
    #pragma unroll
    for (int mt = 0; mt < 2; mt++) {
        #pragma unroll
        for (int nt = 0; nt < 2; nt++) {
            int mloc = wmb + mt * 16 + g;
            int hloc = wnb + nt * 8 + 2 * tg;
            #pragma unroll
            for (int c = 0; c < 4; c++) {
                int m = m0 + mloc + ((c >= 2) ? 8 : 0);
                int h = n0 + hloc + (c & 1);
                float v = acc[mt][nt][c];
                if (which == 0) {
                    g_A[(size_t)m * HH + h] = v + b1[h];
                } else {
                    int b = m >> 7;
                    int j = m & 127;
                    g_Bt[((size_t)b * HH + h) * LL + j] = v;
                }
            }
        }
    }
}

// ----------------------------------------------------------------------------
// Start/end CE losses: one block per (b,i) row. 128 threads, 4 dots of len 768.
// ----------------------------------------------------------------------------
__global__ __launch_bounds__(128)
void startend_kernel(const float* __restrict__ X,
                     const int* __restrict__ sp, const int* __restrict__ ep,
                     const float* __restrict__ Wst, const float* __restrict__ bst,
                     const float* __restrict__ Wen, const float* __restrict__ ben,
                     float* out)
{
    int m = blockIdx.x;
    int tid = threadIdx.x;
    const float* x = X + (size_t)m * HH;

    float s0 = 0.f, s1 = 0.f, e0 = 0.f, e1 = 0.f;
    for (int h = tid; h < HH; h += 128) {
        float xv = x[h];
        s0 = fmaf(xv, Wst[h * 2 + 0], s0);
        s1 = fmaf(xv, Wst[h * 2 + 1], s1);
        e0 = fmaf(xv, Wen[h * 2 + 0], e0);
        e1 = fmaf(xv, Wen[h * 2 + 1], e1);
    }
    #pragma unroll
    for (int off = 16; off > 0; off >>= 1) {
        s0 += __shfl_xor_sync(0xffffffffu, s0, off);
        s1 += __shfl_xor_sync(0xffffffffu, s1, off);
        e0 += __shfl_xor_sync(0xffffffffu, e0, off);
        e1 += __shfl_xor_sync(0xffffffffu, e1, off);
    }
    __shared__ float sh[4][4];
    int warp = tid >> 5, lane = tid & 31;
    if (lane == 0) { sh[0][warp] = s0; sh[1][warp] = s1; sh[2][warp] = e0; sh[3][warp] = e1; }
    __syncthreads();
    if (tid == 0) {
        float l0 = sh[0][0] + sh[0][1] + sh[0][2] + sh[0][3] + bst[0];
        float l1 = sh[1][0] + sh[1][1] + sh[1][2] + sh[1][3] + bst[1];
        float mx = fmaxf(l0, l1);
        float lse = mx + logf(expf(l0 - mx) + expf(l1 - mx));
        float loss_s = lse - (sp[m] == 0 ? l0 : l1);

        float k0v = sh[2][0] + sh[2][1] + sh[2][2] + sh[2][3] + ben[0];
        float k1v = sh[3][0] + sh[3][1] + sh[3][2] + sh[3][3] + ben[1];
        float mx2 = fmaxf(k0v, k1v);
        float lse2 = mx2 + logf(expf(k0v - mx2) + expf(k1v - mx2));
        float loss_e = lse2 - (ep[m] == 0 ? k0v : k1v);

        atomicAdd(out, (loss_s + loss_e) * (1.0f / (float)MM));
    }
}

// ----------------------------------------------------------------------------
// Fast GELU via hardware tanh
// ----------------------------------------------------------------------------
__device__ __forceinline__ float fast_tanh(float x) {
    float y;
    asm("tanh.approx.f32 %0, %1;" : "=f"(y) : "f"(x));
    return y;
}

__device__ __forceinline__ float gelu_fast(float x) {
    float t  = x * x;
    float u  = x * fmaf(0.035677408136300125f, t, 0.7978845608028654f);
    float th = fast_tanh(u);
    float hx = 0.5f * x;
    return fmaf(hx, th, hx);
}

// ----------------------------------------------------------------------------
// Span loss v3: one block per (b,i). 256 threads = 32 j-quads x 8 h-slices.
// Each thread owns 4 consecutive j (one LDG.128 per 4 elements) and a 96-h
// slice; partials combine via an 8x128 smem array, then BCE + block reduce.
// ----------------------------------------------------------------------------
#define HSLICE (HH / 8)     // 96

__global__ __launch_bounds__(256)
void span_kernel(const int* __restrict__ spanp, const float* __restrict__ W2,
                 const float* __restrict__ b2, float* out)
{
    __shared__ __align__(16) float a_sh[HH];
    __shared__ __align__(16) float w2_sh[HH];
    __shared__ __align__(16) float part[8 * 128];

    int m = blockIdx.x;     // b*L + i
    int b = m >> 7;
    int tid = threadIdx.x;
    int jq    = tid & 31;   // j-quad: j = 4*jq .. 4*jq+3
    int slice = tid >> 5;   // h-slice 0..7
    int j0 = jq * 4;

    for (int h = tid; h < HH; h += 256) {
        a_sh[h]  = g_A[(size_t)m * HH + h];
        w2_sh[h] = W2[h];
    }
    __syncthreads();

    const int h0 = slice * HSLICE;
    const float* __restrict__ Bp = g_Bt + ((size_t)b * HH + h0) * LL + j0;
    const float* __restrict__ ap = a_sh + h0;
    const float* __restrict__ wp = w2_sh + h0;

    float acc0 = 0.f, acc1 = 0.f, acc2 = 0.f, acc3 = 0.f;

    #pragma unroll 4
    for (int it = 0; it < HSLICE; it++) {
        float4 bv = *reinterpret_cast<const float4*>(Bp);
        float av = ap[it];
        float wv = wp[it];
        acc0 = fmaf(gelu_fast(av + bv.x), wv, acc0);
        acc1 = fmaf(gelu_fast(av + bv.y), wv, acc1);
        acc2 = fmaf(gelu_fast(av + bv.z), wv, acc2);
        acc3 = fmaf(gelu_fast(av + bv.w), wv, acc3);
        Bp += LL;
    }

    *reinterpret_cast<float4*>(&part[slice * 128 + j0]) =
        make_float4(acc0, acc1, acc2, acc3);
    __syncthreads();

    if (tid < 128) {
        float logit = b2[0];
        #pragma unroll
        for (int s = 0; s < 8; s++) logit += part[s * 128 + tid];

        float z = (float)spanp[(size_t)m * LL + tid];
        float loss = fmaxf(logit, 0.0f) - logit * z + log1pf(expf(-fabsf(logit)));

        #pragma unroll
        for (int off = 16; off > 0; off >>= 1)
            loss += __shfl_xor_sync(0xffffffffu, loss, off);

        __shared__ float ws[4];
        if ((tid & 31) == 0) ws[tid >> 5] = loss;
        __syncthreads();
        if (tid == 0)
            atomicAdd(out, (ws[0] + ws[1] + ws[2] + ws[3]) * (1.0f / (float)(MM * LL)));
    }
}

// ----------------------------------------------------------------------------
extern "C" void kernel_launch(void* const* d_in, const int* in_sizes, int n_in,
                              void* d_out, int out_size)
{
    const float* X     = (const float*)d_in[0];   // sequence_output (B,L,H)
    const int*   sp    = (const int*)  d_in[1];   // start_positions (B,L)
    const int*   ep    = (const int*)  d_in[2];   // end_positions (B,L)
    const int*   spanp = (const int*)  d_in[3];   // span_positions (B,L,L)
    const float* Wst   = (const float*)d_in[4];   // W_start (H,2)
    const float* bst   = (const float*)d_in[5];   // b_start (2)
    const float* Wen   = (const float*)d_in[6];   // W_end (H,2)
    const float* ben   = (const float*)d_in[7];   // b_end (2)
    const float* W1    = (const float*)d_in[8];   // W1 (2H,H)
    const float* b1    = (const float*)d_in[9];   // b1 (H)
    const float* W2    = (const float*)d_in[10];  // W2 (H,1)
    const float* b2    = (const float*)d_in[11];  // b2 (1)
    float* out = (float*)d_out;

    zero_out_kernel<<<1, 1>>>(out);

    dim3 grid(HH / GBN, MM / GBM, 2);   // (12, 16, 2) = 384 blocks
    dual_gemm_tc_kernel<<<grid, 256>>>(X, W1, b1);

    startend_kernel<<<MM, 128>>>(X, sp, ep, Wst, bst, Wen, ben, out);
    span_kernel<<<MM, 256>>>(spanp, W2, b2, out);
}

// round 11
// speedup vs baseline: 2.8733x; 1.0453x over previous
#include <cuda_runtime.h>
#include <math.h>
#include <stdint.h>

// Problem constants (fixed by reference setup_inputs)
#define BB 8
#define LL 128
#define HH 768
#define MM (BB*LL)          // 1024 rows

// Scratch: A[(b*L+i), h] = X@W1_top + b1 ; Bt[b, h, j] = (X@W1_bot) transposed
__device__ float g_A[MM * HH];
__device__ float g_Bt[BB * HH * LL];

// ----------------------------------------------------------------------------
// mma.sync tf32 (raw f32 bits in, HW truncates mantissa)
// ----------------------------------------------------------------------------
__device__ __forceinline__ void mma_tf32_16x8x8(
    float& d0, float& d1, float& d2, float& d3,
    uint32_t a0, uint32_t a1, uint32_t a2, uint32_t a3,
    uint32_t b0, uint32_t b1)
{
    asm volatile(
        "mma.sync.aligned.m16n8k8.row.col.f32.tf32.tf32.f32 "
        "{%0,%1,%2,%3}, {%4,%5,%6,%7}, {%8,%9}, {%0,%1,%2,%3};"
        : "+f"(d0), "+f"(d1), "+f"(d2), "+f"(d3)
        : "r"(a0), "r"(a1), "r"(a2), "r"(a3), "r"(b0), "r"(b1));
}

__device__ __forceinline__ void cp_async16(uint32_t smem_addr, const void* gptr) {
    asm volatile("cp.async.ca.shared.global [%0], [%1], 16;\n"
                 :: "r"(smem_addr), "l"(gptr));
}
__device__ __forceinline__ void cp_async_commit() {
    asm volatile("cp.async.commit_group;\n");
}
template <int N>
__device__ __forceinline__ void cp_async_wait() {
    asm volatile("cp.async.wait_group %0;\n" :: "n"(N));
}

// ----------------------------------------------------------------------------
// Packed f32x2 helpers (Blackwell sm_100+)
// ----------------------------------------------------------------------------
typedef unsigned long long u64;

__device__ __forceinline__ u64 pk2(float lo, float hi) {
    u64 r; asm("mov.b64 %0, {%1, %2};" : "=l"(r) : "f"(lo), "f"(hi)); return r;
}
__device__ __forceinline__ void upk2(u64 v, float& lo, float& hi) {
    asm("mov.b64 {%0, %1}, %2;" : "=f"(lo), "=f"(hi) : "l"(v));
}
__device__ __forceinline__ u64 add2(u64 a, u64 b) {
    u64 r; asm("add.rn.f32x2 %0, %1, %2;" : "=l"(r) : "l"(a), "l"(b)); return r;
}
__device__ __forceinline__ u64 mul2(u64 a, u64 b) {
    u64 r; asm("mul.rn.f32x2 %0, %1, %2;" : "=l"(r) : "l"(a), "l"(b)); return r;
}
__device__ __forceinline__ u64 fma2(u64 a, u64 b, u64 c) {
    u64 r; asm("fma.rn.f32x2 %0, %1, %2, %3;" : "=l"(r) : "l"(a), "l"(b), "l"(c)); return r;
}

__device__ __forceinline__ float fast_tanh(float x) {
    float y;
    asm("tanh.approx.f32 %0, %1;" : "=f"(y) : "f"(x));
    return y;
}

// ----------------------------------------------------------------------------
// Dual GEMM on tensor cores, cp.async double-buffered.
// z=0 -> g_A (+b1), z=1 -> g_Bt (transposed store). Also zeroes out[0].
// ----------------------------------------------------------------------------
#define GBM 64
#define GBN 64
#define GBK 32
#define NKT (HH / GBK)   // 24
#define XS_STRIDE 36
#define WS_STRIDE 72

__global__ __launch_bounds__(256)
void dual_gemm_tc_kernel(const float* __restrict__ X, const float* __restrict__ W1,
                         const float* __restrict__ b1, float* out)
{
    __shared__ uint32_t Xs[2][GBM * XS_STRIDE];   // raw f32 bits
    __shared__ uint32_t Ws[2][GBK * WS_STRIDE];

    const int which = blockIdx.z;
    const float* __restrict__ W = W1 + which * HH * HH;
    const int n0 = blockIdx.x * GBN;
    const int m0 = blockIdx.y * GBM;
    const int t  = threadIdx.x;

    if (which == 0 && blockIdx.x == 0 && blockIdx.y == 0 && t == 0)
        out[0] = 0.0f;   // zero the loss accumulator (later kernels serialize after)

    const int warp = t >> 5;
    const int lane = t & 31;
    const int g   = lane >> 2;
    const int tg  = lane & 3;
    const int wm  = warp & 1;
    const int wn  = warp >> 1;
    const int wmb = wm * 32;
    const int wnb = wn * 16;

    const int xr0 = (t * 4) >> 5;
    const int xc0 = (t * 4) & 31;
    const int xr1 = xr0 + 32;
    const int wk0 = (t * 4) >> 6;
    const int wn0 = (t * 4) & 63;
    const int wk1 = wk0 + 16;

    auto fill = [&](int buf, int k0) {
        cp_async16((uint32_t)__cvta_generic_to_shared(&Xs[buf][xr0 * XS_STRIDE + xc0]),
                   &X[(size_t)(m0 + xr0) * HH + k0 + xc0]);
        cp_async16((uint32_t)__cvta_generic_to_shared(&Xs[buf][xr1 * XS_STRIDE + xc0]),
                   &X[(size_t)(m0 + xr1) * HH + k0 + xc0]);
        cp_async16((uint32_t)__cvta_generic_to_shared(&Ws[buf][wk0 * WS_STRIDE + wn0]),
                   &W[(size_t)(k0 + wk0) * HH + n0 + wn0]);
        cp_async16((uint32_t)__cvta_generic_to_shared(&Ws[buf][wk1 * WS_STRIDE + wn0]),
                   &W[(size_t)(k0 + wk1) * HH + n0 + wn0]);
    };

    float acc[2][2][4];
    #pragma unroll
    for (int mt = 0; mt < 2; mt++)
        #pragma unroll
        for (int nt = 0; nt < 2; nt++)
            #pragma unroll
            for (int c = 0; c < 4; c++) acc[mt][nt][c] = 0.0f;

    fill(0, 0);
    cp_async_commit();

    for (int kt = 0; kt < NKT; kt++) {
        if (kt + 1 < NKT) {
            fill((kt + 1) & 1, (kt + 1) * GBK);
            cp_async_commit();
            cp_async_wait<1>();
        } else {
            cp_async_wait<0>();
        }
        __syncthreads();

        const uint32_t* xs = Xs[kt & 1];
        const uint32_t* ws = Ws[kt & 1];

        #pragma unroll
        for (int k8 = 0; k8 < GBK; k8 += 8) {
            uint32_t af[2][4];
            #pragma unroll
            for (int mt = 0; mt < 2; mt++) {
                int r0 = wmb + mt * 16 + g;
                af[mt][0] = xs[r0 * XS_STRIDE + k8 + tg];
                af[mt][1] = xs[(r0 + 8) * XS_STRIDE + k8 + tg];
                af[mt][2] = xs[r0 * XS_STRIDE + k8 + tg + 4];
                af[mt][3] = xs[(r0 + 8) * XS_STRIDE + k8 + tg + 4];
            }
            uint32_t bfr[2][2];
            #pragma unroll
            for (int nt = 0; nt < 2; nt++) {
                int c0 = wnb + nt * 8 + g;
                bfr[nt][0] = ws[(k8 + tg) * WS_STRIDE + c0];
                bfr[nt][1] = ws[(k8 + tg + 4) * WS_STRIDE + c0];
            }
            #pragma unroll
            for (int mt = 0; mt < 2; mt++)
                #pragma unroll
                for (int nt = 0; nt < 2; nt++)
                    mma_tf32_16x8x8(acc[mt][nt][0], acc[mt][nt][1],
                                    acc[mt][nt][2], acc[mt][nt][3],
                                    af[mt][0], af[mt][1], af[mt][2], af[mt][3],
                                    bfr[nt][0], bfr[nt][1]);
        }
        __syncthreads();
    }

    #pragma unroll
    for (int mt = 0; mt < 2; mt++) {
        #pragma unroll
        for (int nt = 0; nt < 2; nt++) {
            int mloc = wmb + mt * 16 + g;
            int hloc = wnb + nt * 8 + 2 * tg;
            #pragma unroll
            for (int c = 0; c < 4; c++) {
                int m = m0 + mloc + ((c >= 2) ? 8 : 0);
                int h = n0 + hloc + (c & 1);
                float v = acc[mt][nt][c];
                if (which == 0) {
                    g_A[(size_t)m * HH + h] = v + b1[h];
                } else {
                    int b = m >> 7;
                    int j = m & 127;
                    g_Bt[((size_t)b * HH + h) * LL + j] = v;
                }
            }
        }
    }
}

// ----------------------------------------------------------------------------
// Start/end CE losses: one block per (b,i) row. 128 threads, 4 dots of len 768.
// ----------------------------------------------------------------------------
__global__ __launch_bounds__(128)
void startend_kernel(const float* __restrict__ X,
                     const int* __restrict__ sp, const int* __restrict__ ep,
                     const float* __restrict__ Wst, const float* __restrict__ bst,
                     const float* __restrict__ Wen, const float* __restrict__ ben,
                     float* out)
{
    int m = blockIdx.x;
    int tid = threadIdx.x;
    const float* x = X + (size_t)m * HH;

    float s0 = 0.f, s1 = 0.f, e0 = 0.f, e1 = 0.f;
    for (int h = tid; h < HH; h += 128) {
        float xv = x[h];
        s0 = fmaf(xv, Wst[h * 2 + 0], s0);
        s1 = fmaf(xv, Wst[h * 2 + 1], s1);
        e0 = fmaf(xv, Wen[h * 2 + 0], e0);
        e1 = fmaf(xv, Wen[h * 2 + 1], e1);
    }
    #pragma unroll
    for (int off = 16; off > 0; off >>= 1) {
        s0 += __shfl_xor_sync(0xffffffffu, s0, off);
        s1 += __shfl_xor_sync(0xffffffffu, s1, off);
        e0 += __shfl_xor_sync(0xffffffffu, e0, off);
        e1 += __shfl_xor_sync(0xffffffffu, e1, off);
    }
    __shared__ float sh[4][4];
    int warp = tid >> 5, lane = tid & 31;
    if (lane == 0) { sh[0][warp] = s0; sh[1][warp] = s1; sh[2][warp] = e0; sh[3][warp] = e1; }
    __syncthreads();
    if (tid == 0) {
        float l0 = sh[0][0] + sh[0][1] + sh[0][2] + sh[0][3] + bst[0];
        float l1 = sh[1][0] + sh[1][1] + sh[1][2] + sh[1][3] + bst[1];
        float mx = fmaxf(l0, l1);
        float lse = mx + logf(expf(l0 - mx) + expf(l1 - mx));
        float loss_s = lse - (sp[m] == 0 ? l0 : l1);

        float k0v = sh[2][0] + sh[2][1] + sh[2][2] + sh[2][3] + ben[0];
        float k1v = sh[3][0] + sh[3][1] + sh[3][2] + sh[3][3] + ben[1];
        float mx2 = fmaxf(k0v, k1v);
        float lse2 = mx2 + logf(expf(k0v - mx2) + expf(k1v - mx2));
        float loss_e = lse2 - (ep[m] == 0 ? k0v : k1v);

        atomicAdd(out, (loss_s + loss_e) * (1.0f / (float)MM));
    }
}

// ----------------------------------------------------------------------------
// Span loss v4: packed f32x2 gelu+dot.
// One block per (b,i). 256 threads = 32 j-quads x 8 h-slices.
// Each thread owns 4 consecutive j as TWO f32x2 pairs (Bt loaded as ulonglong2
// = pre-packed pairs), and a 96-h slice.
// gelu(x)*w = p + p*tanh(u), p = x*(w/2), u = x*(c1*x^2 + c0)
// => per 2 elems: 7 packed fma-class ops + 2 MUFU tanh + 2 movs.
// ----------------------------------------------------------------------------
#define HSLICE (HH / 8)     // 96

__global__ __launch_bounds__(256)
void span_kernel(const int* __restrict__ spanp, const float* __restrict__ W2,
                 const float* __restrict__ b2, float* out)
{
    __shared__ __align__(16) float a_sh[HH];
    __shared__ __align__(16) float w2_sh[HH];
    __shared__ __align__(16) float part[8 * 128];

    int m = blockIdx.x;     // b*L + i
    int b = m >> 7;
    int tid = threadIdx.x;
    int jq    = tid & 31;   // j-quad: j = 4*jq .. 4*jq+3
    int slice = tid >> 5;   // h-slice 0..7
    int j0 = jq * 4;

    for (int h = tid; h < HH; h += 256) {
        a_sh[h]  = g_A[(size_t)m * HH + h];
        w2_sh[h] = W2[h];
    }
    __syncthreads();

    const int h0 = slice * HSLICE;
    const float* __restrict__ Bp = g_Bt + ((size_t)b * HH + h0) * LL + j0;
    const float* __restrict__ ap = a_sh + h0;
    const float* __restrict__ wp = w2_sh + h0;

    const u64 C1 = pk2(0.035677408136300125f, 0.035677408136300125f);
    const u64 C0 = pk2(0.7978845608028654f,   0.7978845608028654f);

    u64 accL0 = 0, accT0 = 0, accL1 = 0, accT1 = 0;   // 0.0f|0.0f packed

    #pragma unroll 4
    for (int it = 0; it < HSLICE; it++) {
        ulonglong2 bv = *reinterpret_cast<const ulonglong2*>(Bp);  // (b0,b1),(b2,b3)
        float a  = ap[it];
        float hw = 0.5f * wp[it];
        u64 aa  = pk2(a, a);
        u64 hw2 = pk2(hw, hw);

        // pair 0: j0,j1
        {
            u64 x = add2(aa, bv.x);
            u64 t = mul2(x, x);
            u64 u = mul2(fma2(t, C1, C0), x);
            float ul, uh; upk2(u, ul, uh);
            u64 th = pk2(fast_tanh(ul), fast_tanh(uh));
            u64 p = mul2(x, hw2);
            accL0 = add2(accL0, p);
            accT0 = fma2(p, th, accT0);
        }
        // pair 1: j2,j3
        {
            u64 x = add2(aa, bv.y);
            u64 t = mul2(x, x);
            u64 u = mul2(fma2(t, C1, C0), x);
            float ul, uh; upk2(u, ul, uh);
            u64 th = pk2(fast_tanh(ul), fast_tanh(uh));
            u64 p = mul2(x, hw2);
            accL1 = add2(accL1, p);
            accT1 = fma2(p, th, accT1);
        }
        Bp += LL;
    }

    float l0, l1, l2, l3, t0, t1, t2, t3;
    upk2(accL0, l0, l1); upk2(accT0, t0, t1);
    upk2(accL1, l2, l3); upk2(accT1, t2, t3);
    *reinterpret_cast<float4*>(&part[slice * 128 + j0]) =
        make_float4(l0 + t0, l1 + t1, l2 + t2, l3 + t3);
    __syncthreads();

    if (tid < 128) {
        float logit = b2[0];
        #pragma unroll
        for (int s = 0; s < 8; s++) logit += part[s * 128 + tid];

        float z = (float)spanp[(size_t)m * LL + tid];
        float loss = fmaxf(logit, 0.0f) - logit * z + log1pf(expf(-fabsf(logit)));

        #pragma unroll
        for (int off = 16; off > 0; off >>= 1)
            loss += __shfl_xor_sync(0xffffffffu, loss, off);

        __shared__ float ws[4];
        if ((tid & 31) == 0) ws[tid >> 5] = loss;
        __syncthreads();
        if (tid == 0)
            atomicAdd(out, (ws[0] + ws[1] + ws[2] + ws[3]) * (1.0f / (float)(MM * LL)));
    }
}

// ----------------------------------------------------------------------------
extern "C" void kernel_launch(void* const* d_in, const int* in_sizes, int n_in,
                              void* d_out, int out_size)
{
    const float* X     = (const float*)d_in[0];   // sequence_output (B,L,H)
    const int*   sp    = (const int*)  d_in[1];   // start_positions (B,L)
    const int*   ep    = (const int*)  d_in[2];   // end_positions (B,L)
    const int*   spanp = (const int*)  d_in[3];   // span_positions (B,L,L)
    const float* Wst   = (const float*)d_in[4];   // W_start (H,2)
    const float* bst   = (const float*)d_in[5];   // b_start (2)
    const float* Wen   = (const float*)d_in[6];   // W_end (H,2)
    const float* ben   = (const float*)d_in[7];   // b_end (2)
    const float* W1    = (const float*)d_in[8];   // W1 (2H,H)
    const float* b1    = (const float*)d_in[9];   // b1 (H)
    const float* W2    = (const float*)d_in[10];  // W2 (H,1)
    const float* b2    = (const float*)d_in[11];  // b2 (1)
    float* out = (float*)d_out;

    dim3 grid(HH / GBN, MM / GBM, 2);   // (12, 16, 2) = 384 blocks
    dual_gemm_tc_kernel<<<grid, 256>>>(X, W1, b1, out);

    startend_kernel<<<MM, 128>>>(X, sp, ep, Wst, bst, Wen, ben, out);
    span_kernel<<<MM, 256>>>(spanp, W2, b2, out);
}